// round 1
// baseline (speedup 1.0000x reference)
#include <cuda_runtime.h>
#include <math.h>

#define DIMC    512
#define HEADS   8
#define HDIM    64
#define WSZ     4
#define NWA     8          // RES/WS
#define PWIN    64         // WS^3
#define NPTS    32768      // 32^3
#define NWIN    512        // NPTS/PWIN
#define TAB     343        // (2*WS-1)^3

// ---------------- scratch (device globals; no allocations allowed) ----------
__device__ int   g_cnt[NWIN];
__device__ int   g_order[NPTS];          // sorted pos -> original row
__device__ int   g_cs[NPTS * 3];         // coords in sorted order
__device__ float g_q[NPTS * DIMC];       // [w][h][p][d]
__device__ float g_k[NPTS * DIMC];
__device__ float g_v[NPTS * DIMC];
__device__ float g_attn[NPTS * DIMC];    // [s][h*64+d]  (row-major N x C)

// ---------------- kernel 1: zero window counters ----------------------------
__global__ void zero_cnt_kernel() {
    int t = blockIdx.x * blockDim.x + threadIdx.x;
    if (t < NWIN) g_cnt[t] = 0;
}

// ---------------- kernel 2: bucket-rank window ordering ----------------------
__global__ void build_order_kernel(const int* __restrict__ coords, int N) {
    int i = blockIdx.x * blockDim.x + threadIdx.x;
    if (i >= N) return;
    int c0 = coords[3 * i + 0];
    int c1 = coords[3 * i + 1];
    int c2 = coords[3 * i + 2];
    int w  = ((c0 >> 2) * NWA + (c1 >> 2)) * NWA + (c2 >> 2);
    int rank = atomicAdd(&g_cnt[w], 1);
    int s = (w << 6) + rank;
    g_order[s]      = i;
    g_cs[3 * s + 0] = c0;
    g_cs[3 * s + 1] = c1;
    g_cs[3 * s + 2] = c2;
}

// ---------------- kernel 3: QKV GEMM (gathered A), 128x128x8 tiles -----------
// C[s, c] = x[order[s], :] @ w_qkv[:, c] + b_qkv[c], scattered to q/k/v bufs.
__global__ __launch_bounds__(256) void qkv_gemm_kernel(
    const float* __restrict__ x,
    const float* __restrict__ wq,
    const float* __restrict__ bq)
{
    __shared__ float As[8][128];
    __shared__ float Bs[8][128];
    __shared__ int   rows[128];

    const int tid = threadIdx.x;
    const int bx  = blockIdx.x;   // 12 column tiles (1536/128)
    const int by  = blockIdx.y;   // 256 row tiles

    if (tid < 128) rows[tid] = g_order[by * 128 + tid];
    __syncthreads();

    const int tr = tid >> 4;      // 0..15
    const int tc = tid & 15;      // 0..15
    const int c0 = bx * 128;

    const int ar = tid >> 1;              // 0..127 (A row within tile)
    const int ak = (tid & 1) * 4;         // 0 or 4
    const int bk = tid >> 5;              // 0..7
    const int bc = (tid & 31) * 4;        // 0..124

    const float* xrow = x + (size_t)rows[ar] * DIMC + ak;

    float acc[8][8];
#pragma unroll
    for (int i = 0; i < 8; i++)
#pragma unroll
        for (int j = 0; j < 8; j++) acc[i][j] = 0.f;

    for (int k0 = 0; k0 < DIMC; k0 += 8) {
        float4 a4 = *(const float4*)(xrow + k0);
        As[ak + 0][ar] = a4.x;
        As[ak + 1][ar] = a4.y;
        As[ak + 2][ar] = a4.z;
        As[ak + 3][ar] = a4.w;
        float4 b4 = *(const float4*)&wq[(size_t)(k0 + bk) * 1536 + c0 + bc];
        *(float4*)&Bs[bk][bc] = b4;
        __syncthreads();
#pragma unroll
        for (int kk = 0; kk < 8; kk++) {
            float4 a0 = *(const float4*)&As[kk][tr * 8];
            float4 a1 = *(const float4*)&As[kk][tr * 8 + 4];
            float4 b0 = *(const float4*)&Bs[kk][tc * 8];
            float4 b1 = *(const float4*)&Bs[kk][tc * 8 + 4];
            float a[8] = {a0.x, a0.y, a0.z, a0.w, a1.x, a1.y, a1.z, a1.w};
            float b[8] = {b0.x, b0.y, b0.z, b0.w, b1.x, b1.y, b1.z, b1.w};
#pragma unroll
            for (int i = 0; i < 8; i++)
#pragma unroll
                for (int j = 0; j < 8; j++) acc[i][j] += a[i] * b[j];
        }
        __syncthreads();
    }

    // epilogue: scatter into q/k/v as [w][h][p][d]
#pragma unroll
    for (int i = 0; i < 8; i++) {
        int s = by * 128 + tr * 8 + i;
        int w = s >> 6;
        int p = s & 63;
#pragma unroll
        for (int j = 0; j < 8; j++) {
            int c = c0 + tc * 8 + j;
            float v = acc[i][j] + bq[c];
            int which = c >> 9;          // 0=q,1=k,2=v
            int h     = (c >> 6) & 7;
            int d     = c & 63;
            float* dst = (which == 0) ? g_q : (which == 1) ? g_k : g_v;
            dst[(((w * 8 + h) * 64) + p) * 64 + d] = v;
        }
    }
}

// ---------------- kernel 4: per-(window, head) attention ---------------------
// 64 threads, 8x8 micro-tile each. S computed in registers, softmax via shfl.
__global__ __launch_bounds__(64) void attn_kernel(const float* __restrict__ rpb) {
    __shared__ float bufA[64 * 65];   // Q, then V
    __shared__ float bufB[64 * 65];   // K, then S
    __shared__ int   csm[64 * 3];
    __shared__ float bsm[TAB];

    const int b  = blockIdx.x;
    const int w  = b >> 3;
    const int h  = b & 7;
    const int tid = threadIdx.x;

    const size_t base = ((size_t)(w * 8 + h)) << 12;   // (w*8+h)*64*64
    const float* Qg = g_q + base;
    const float* Kg = g_k + base;
    const float* Vg = g_v + base;

    // load Q -> bufA, K -> bufB (padded LD=65)
#pragma unroll
    for (int t = 0; t < 16; t++) {
        int e = (tid + t * 64) * 4;
        int p = e >> 6, d = e & 63;
        float4 qa = *(const float4*)(Qg + e);
        bufA[p * 65 + d + 0] = qa.x;
        bufA[p * 65 + d + 1] = qa.y;
        bufA[p * 65 + d + 2] = qa.z;
        bufA[p * 65 + d + 3] = qa.w;
        float4 ka = *(const float4*)(Kg + e);
        bufB[p * 65 + d + 0] = ka.x;
        bufB[p * 65 + d + 1] = ka.y;
        bufB[p * 65 + d + 2] = ka.z;
        bufB[p * 65 + d + 3] = ka.w;
    }
    for (int t = tid; t < 192; t += 64) csm[t] = g_cs[w * 192 + t];
    for (int t = tid; t < TAB; t += 64) bsm[t] = rpb[t * HEADS + h];
    __syncthreads();

    const int ty = tid >> 3;   // 0..7 : rows p = ty*8+i
    const int tx = tid & 7;    // 0..7 : cols q = tx*8+j

    float acc[8][8];
#pragma unroll
    for (int i = 0; i < 8; i++)
#pragma unroll
        for (int j = 0; j < 8; j++) acc[i][j] = 0.f;

    // S = Q K^T
#pragma unroll 4
    for (int k = 0; k < 64; k++) {
        float a[8], bb[8];
#pragma unroll
        for (int i = 0; i < 8; i++) a[i]  = bufA[(ty * 8 + i) * 65 + k];
#pragma unroll
        for (int j = 0; j < 8; j++) bb[j] = bufB[(tx * 8 + j) * 65 + k];
#pragma unroll
        for (int i = 0; i < 8; i++)
#pragma unroll
            for (int j = 0; j < 8; j++) acc[i][j] += a[i] * bb[j];
    }

    // column coords for this thread's 8 cols
    int cq0[8], cq1[8], cq2[8];
#pragma unroll
    for (int j = 0; j < 8; j++) {
        int q = tx * 8 + j;
        cq0[j] = csm[q * 3 + 0];
        cq1[j] = csm[q * 3 + 1];
        cq2[j] = csm[q * 3 + 2];
    }

    // scale + bias + softmax (rows split across 8 lanes with same ty)
#pragma unroll
    for (int i = 0; i < 8; i++) {
        int p = ty * 8 + i;
        int cp0 = csm[p * 3 + 0], cp1 = csm[p * 3 + 1], cp2 = csm[p * 3 + 2];
        float m = -1e30f;
#pragma unroll
        for (int j = 0; j < 8; j++) {
            int r0 = cp0 - cq0[j] + (WSZ - 1);
            int r1 = cp1 - cq1[j] + (WSZ - 1);
            int r2 = cp2 - cq2[j] + (WSZ - 1);
            int ridx = (r0 * 7 + r1) * 7 + r2;
            float v = acc[i][j] * 0.125f + bsm[ridx];
            acc[i][j] = v;
            m = fmaxf(m, v);
        }
        m = fmaxf(m, __shfl_xor_sync(0xffffffffu, m, 1));
        m = fmaxf(m, __shfl_xor_sync(0xffffffffu, m, 2));
        m = fmaxf(m, __shfl_xor_sync(0xffffffffu, m, 4));
        float s = 0.f;
#pragma unroll
        for (int j = 0; j < 8; j++) {
            float e = expf(acc[i][j] - m);
            acc[i][j] = e;
            s += e;
        }
        s += __shfl_xor_sync(0xffffffffu, s, 1);
        s += __shfl_xor_sync(0xffffffffu, s, 2);
        s += __shfl_xor_sync(0xffffffffu, s, 4);
        float r = 1.f / s;
#pragma unroll
        for (int j = 0; j < 8; j++) acc[i][j] *= r;
    }

    __syncthreads();   // everyone done reading Q/K tiles

    // store S into bufB, load V into bufA
#pragma unroll
    for (int i = 0; i < 8; i++)
#pragma unroll
        for (int j = 0; j < 8; j++)
            bufB[(ty * 8 + i) * 65 + tx * 8 + j] = acc[i][j];
#pragma unroll
    for (int t = 0; t < 16; t++) {
        int e = (tid + t * 64) * 4;
        int p = e >> 6, d = e & 63;
        float4 va = *(const float4*)(Vg + e);
        bufA[p * 65 + d + 0] = va.x;
        bufA[p * 65 + d + 1] = va.y;
        bufA[p * 65 + d + 2] = va.z;
        bufA[p * 65 + d + 3] = va.w;
    }
    __syncthreads();

    // O = S V
    float o[8][8];
#pragma unroll
    for (int i = 0; i < 8; i++)
#pragma unroll
        for (int j = 0; j < 8; j++) o[i][j] = 0.f;
#pragma unroll 4
    for (int q = 0; q < 64; q++) {
        float a[8], bb[8];
#pragma unroll
        for (int i = 0; i < 8; i++) a[i]  = bufB[(ty * 8 + i) * 65 + q];
#pragma unroll
        for (int j = 0; j < 8; j++) bb[j] = bufA[q * 65 + tx * 8 + j];
#pragma unroll
        for (int i = 0; i < 8; i++)
#pragma unroll
            for (int j = 0; j < 8; j++) o[i][j] += a[i] * bb[j];
    }

    // write to g_attn[s][h*64+d], row-major N x 512
#pragma unroll
    for (int i = 0; i < 8; i++) {
        int p = ty * 8 + i;
        size_t ob = (size_t)(w * 64 + p) * DIMC + h * 64 + tx * 8;
        *(float4*)&g_attn[ob]     = make_float4(o[i][0], o[i][1], o[i][2], o[i][3]);
        *(float4*)&g_attn[ob + 4] = make_float4(o[i][4], o[i][5], o[i][6], o[i][7]);
    }
}

// ---------------- kernel 5: proj GEMM + row scatter --------------------------
__global__ __launch_bounds__(256) void proj_gemm_kernel(
    const float* __restrict__ wp,
    const float* __restrict__ bp,
    float* __restrict__ out)
{
    __shared__ float As[8][128];
    __shared__ float Bs[8][128];
    __shared__ int   rows[128];

    const int tid = threadIdx.x;
    const int bx  = blockIdx.x;   // 4 column tiles (512/128)
    const int by  = blockIdx.y;   // 256 row tiles

    if (tid < 128) rows[tid] = g_order[by * 128 + tid];
    __syncthreads();

    const int tr = tid >> 4;
    const int tc = tid & 15;
    const int c0 = bx * 128;

    const int ar = tid >> 1;
    const int ak = (tid & 1) * 4;
    const int bk = tid >> 5;
    const int bc = (tid & 31) * 4;

    const float* arow = g_attn + (size_t)(by * 128 + ar) * DIMC + ak;

    float acc[8][8];
#pragma unroll
    for (int i = 0; i < 8; i++)
#pragma unroll
        for (int j = 0; j < 8; j++) acc[i][j] = 0.f;

    for (int k0 = 0; k0 < DIMC; k0 += 8) {
        float4 a4 = *(const float4*)(arow + k0);
        As[ak + 0][ar] = a4.x;
        As[ak + 1][ar] = a4.y;
        As[ak + 2][ar] = a4.z;
        As[ak + 3][ar] = a4.w;
        float4 b4 = *(const float4*)&wp[(size_t)(k0 + bk) * DIMC + c0 + bc];
        *(float4*)&Bs[bk][bc] = b4;
        __syncthreads();
#pragma unroll
        for (int kk = 0; kk < 8; kk++) {
            float4 a0 = *(const float4*)&As[kk][tr * 8];
            float4 a1 = *(const float4*)&As[kk][tr * 8 + 4];
            float4 b0 = *(const float4*)&Bs[kk][tc * 8];
            float4 b1 = *(const float4*)&Bs[kk][tc * 8 + 4];
            float a[8] = {a0.x, a0.y, a0.z, a0.w, a1.x, a1.y, a1.z, a1.w};
            float b[8] = {b0.x, b0.y, b0.z, b0.w, b1.x, b1.y, b1.z, b1.w};
#pragma unroll
            for (int i = 0; i < 8; i++)
#pragma unroll
                for (int j = 0; j < 8; j++) acc[i][j] += a[i] * b[j];
        }
        __syncthreads();
    }

#pragma unroll
    for (int i = 0; i < 8; i++) {
        int orow = rows[tr * 8 + i];
        size_t ob = (size_t)orow * DIMC + c0 + tc * 8;
        float4 v0 = make_float4(acc[i][0] + bp[c0 + tc * 8 + 0],
                                acc[i][1] + bp[c0 + tc * 8 + 1],
                                acc[i][2] + bp[c0 + tc * 8 + 2],
                                acc[i][3] + bp[c0 + tc * 8 + 3]);
        float4 v1 = make_float4(acc[i][4] + bp[c0 + tc * 8 + 4],
                                acc[i][5] + bp[c0 + tc * 8 + 5],
                                acc[i][6] + bp[c0 + tc * 8 + 6],
                                acc[i][7] + bp[c0 + tc * 8 + 7]);
        *(float4*)&out[ob]     = v0;
        *(float4*)&out[ob + 4] = v1;
    }
}

// ---------------- launch -----------------------------------------------------
extern "C" void kernel_launch(void* const* d_in, const int* in_sizes, int n_in,
                              void* d_out, int out_size)
{
    const float* x      = (const float*)d_in[0];
    const int*   coords = (const int*)d_in[1];
    const float* w_qkv  = (const float*)d_in[2];
    const float* b_qkv  = (const float*)d_in[3];
    const float* w_proj = (const float*)d_in[4];
    const float* b_proj = (const float*)d_in[5];
    const float* rpb    = (const float*)d_in[6];
    float* out = (float*)d_out;

    const int N = in_sizes[0] / DIMC;   // 32768

    zero_cnt_kernel<<<2, 256>>>();
    build_order_kernel<<<(N + 255) / 256, 256>>>(coords, N);
    qkv_gemm_kernel<<<dim3(12, N / 128), 256>>>(x, w_qkv, b_qkv);
    attn_kernel<<<(N / PWIN) * HEADS, 64>>>(rpb);
    proj_gemm_kernel<<<dim3(4, N / 128), 256>>>(w_proj, b_proj, out);
}